// round 4
// baseline (speedup 1.0000x reference)
#include <cuda_runtime.h>
#include <math.h>
#include <stdint.h>

#define Bb 128
#define Mm 200
#define Ss 20
#define Qq 20
#define Vv 50000
#define Dd 128
#define NT 4          // max_hops + 1 tables

// -------- device scratch (static allocation; no cudaMalloc allowed) --------
__device__ float g_u[Bb * Dd];                              // 64 KB
__device__ float g_mt[(long)NT * Bb * Mm * Dd];             // 52.4 MB
// A fragments (tf32 hi/lo) in mma-fragment order: [r(8)][ks(16)][lane(32)][4]
__device__ float g_uh[8 * 16 * 32 * 4];                     // 64 KB
__device__ float g_ul[8 * 16 * 32 * 4];                     // 64 KB

// ============================================================
// Kernel 1: u = sum over query tokens of E[0] rows.  grid=B, block=D
// ============================================================
__global__ void k_query_u(const int* __restrict__ query,
                          const float* __restrict__ E) {
    int b = blockIdx.x, d = threadIdx.x;
    __shared__ int q[Qq];
    if (d < Qq) q[d] = query[b * Qq + d];
    __syncthreads();
    float acc = 0.f;
#pragma unroll
    for (int i = 0; i < Qq; i++)
        acc += E[(long)q[i] * Dd + d];
    g_u[b * Dd + d] = acc;
}

// ============================================================
// Kernel 2: mt[t][b][i][d] = sum_s E[t][story[b,i,s]][d] + T[t][i][d]
// One warp per (t,b,i), table-major grid (one table hot in L2 at a time).
// ============================================================
#define SS_WPB 8
__global__ void __launch_bounds__(SS_WPB * 32) k_story_sums(
        const int* __restrict__ story,
        const float* __restrict__ E,
        const float* __restrict__ T) {
    long gw = (long)blockIdx.x * SS_WPB + (threadIdx.x >> 5);
    int lane = threadIdx.x & 31;
    int t = (int)(gw / ((long)Bb * Mm));
    int rem = (int)(gw - (long)t * Bb * Mm);
    int b = rem / Mm, i = rem - b * Mm;

    int tok = (lane < Ss) ? story[((long)b * Mm + i) * Ss + lane] : 0;

    const float4* Et = (const float4*)(E + (long)t * Vv * Dd);
    float4 acc = ((const float4*)(T + ((long)t * Mm + i) * Dd))[lane];
#pragma unroll
    for (int s = 0; s < Ss; s++) {
        int id = __shfl_sync(0xffffffffu, tok, s);
        float4 r = Et[(long)id * 32 + lane];
        acc.x += r.x; acc.y += r.y; acc.z += r.z; acc.w += r.w;
    }
    ((float4*)(g_mt + (((long)t * Bb + b) * Mm + i) * Dd))[lane] = acc;
}

// ============================================================
// Kernel 3: all 3 hops fused. grid=B, block=1024. u lives in smem.
// ============================================================
__global__ void __launch_bounds__(1024) k_hops() {
    __shared__ float su[Dd];
    __shared__ float sc[Mm];
    __shared__ float red[32];
    __shared__ float bc[2];
    __shared__ float op[1024];
    int b = blockIdx.x, tid = threadIdx.x;
    int w = tid >> 5, lane = tid & 31;

    if (tid < Dd) su[tid] = g_u[b * Dd + tid];
    __syncthreads();

    for (int hop = 0; hop < NT - 1; hop++) {
        const float* mt = g_mt + (((long)hop * Bb + b) * Mm) * Dd;
        float4 uu = ((const float4*)su)[lane];
        for (int i = w; i < Mm; i += 32) {
            const float4* row = (const float4*)(mt + (long)i * Dd);
            float4 r = row[lane];
            float p = r.x * uu.x + r.y * uu.y + r.z * uu.z + r.w * uu.w;
#pragma unroll
            for (int o = 16; o; o >>= 1) p += __shfl_xor_sync(0xffffffffu, p, o);
            if (lane == 0) sc[i] = p;
        }
        __syncthreads();

        float v = (tid < Mm) ? sc[tid] : -INFINITY;
        float m = v;
#pragma unroll
        for (int o = 16; o; o >>= 1) m = fmaxf(m, __shfl_xor_sync(0xffffffffu, m, o));
        if (lane == 0) red[w] = m;
        __syncthreads();
        if (w == 0) {
            float t = red[lane];
#pragma unroll
            for (int o = 16; o; o >>= 1) t = fmaxf(t, __shfl_xor_sync(0xffffffffu, t, o));
            if (lane == 0) bc[0] = t;
        }
        __syncthreads();
        float e = (tid < Mm) ? expf(v - bc[0]) : 0.f;
        float s = e;
#pragma unroll
        for (int o = 16; o; o >>= 1) s += __shfl_xor_sync(0xffffffffu, s, o);
        if (lane == 0) red[w] = s;
        __syncthreads();
        if (w == 0) {
            float t = red[lane];
#pragma unroll
            for (int o = 16; o; o >>= 1) t += __shfl_xor_sync(0xffffffffu, t, o);
            if (lane == 0) bc[1] = 1.f / t;
        }
        __syncthreads();
        if (tid < Mm) sc[tid] = e * bc[1];
        __syncthreads();

        const float* mtn = g_mt + (((long)(hop + 1) * Bb + b) * Mm) * Dd;
        int part = tid >> 7, d = tid & 127;
        float acc = 0.f;
        int i0 = part * 25;
#pragma unroll
        for (int i = i0; i < i0 + 25; i++)
            acc += sc[i] * mtn[(long)i * Dd + d];
        op[tid] = acc;
        __syncthreads();
        if (tid < Dd) {
            float o = 0.f;
#pragma unroll
            for (int p = 0; p < 8; p++) o += op[p * 128 + tid];
            su[tid] += o;
        }
        __syncthreads();
    }
    if (tid < Dd) g_u[b * Dd + tid] = su[tid];
}

// ============================================================
// tf32 split helper
// ============================================================
__device__ __forceinline__ void tf32_split(float x, uint32_t& hi, uint32_t& lo) {
    asm("cvt.rna.tf32.f32 %0, %1;" : "=r"(hi) : "f"(x));
    float l = x - __uint_as_float(hi);
    asm("cvt.rna.tf32.f32 %0, %1;" : "=r"(lo) : "f"(l));
}
#define MMA_TF32(c, a0, a1, a2, a3, b0, b1) \
    asm volatile("mma.sync.aligned.m16n8k8.row.col.f32.tf32.tf32.f32 " \
        "{%0,%1,%2,%3}, {%4,%5,%6,%7}, {%8,%9}, {%0,%1,%2,%3};" \
        : "+f"((c)[0]), "+f"((c)[1]), "+f"((c)[2]), "+f"((c)[3]) \
        : "r"(a0), "r"(a1), "r"(a2), "r"(a3), "r"(b0), "r"(b1))

// ============================================================
// Kernel 3.5: split u into tf32 hi/lo fragments (fragment order).
// 4096 frag slots: slot = ((r*16 + ks)*32 + lane); 4 hi + 4 lo floats each.
// ============================================================
__global__ void __launch_bounds__(256) k_split_u() {
    int slot = blockIdx.x * 256 + threadIdx.x;   // 0..4095
    int lane = slot & 31, ks = (slot >> 5) & 15, r = slot >> 9;
    int g = lane >> 2, tg = lane & 3;
    int m = r * 16 + g;
    int k = ks * 8 + tg;
    float a0 = g_u[m * Dd + k];
    float a1 = g_u[(m + 8) * Dd + k];
    float a2 = g_u[m * Dd + k + 4];
    float a3 = g_u[(m + 8) * Dd + k + 4];
    uint32_t h0, l0, h1, l1, h2, l2, h3, l3;
    tf32_split(a0, h0, l0); tf32_split(a1, h1, l1);
    tf32_split(a2, h2, l2); tf32_split(a3, h3, l3);
    ((uint4*)g_uh)[slot] = make_uint4(h0, h1, h2, h3);
    ((uint4*)g_ul)[slot] = make_uint4(l0, l1, l2, l3);
}

// ============================================================
// Kernel 4: ahat = u @ E3^T, 3xTF32 mma with ZERO mainloop conversions.
// Block: 128M x 64N, 256 thr (8 warps as 4x2, each 32Mx32N).
// smem: A hi frags 64KB + A lo frags 64KB + B frags 64KB = 192KB.
// ============================================================
#define GSM2 (3 * 65536)

__global__ void __launch_bounds__(256, 1)
k_gemm_mma(const float* __restrict__ E3, float* __restrict__ ahat) {
    extern __shared__ float sm[];
    uint4* sAh = (uint4*)sm;                  // [8][16][32] frag hi
    uint4* sAl = sAh + 4096;                  // [8][16][32] frag lo
    uint4* sBf = sAl + 4096;                  // [8][16][32] {b0h,b1h,b0l,b1l}
    int tid = threadIdx.x, lane = tid & 31, wid = tid >> 5;
    int wm = wid & 3, wn = wid >> 2;
    int v0 = blockIdx.x * 64;

    // ---- copy prefabricated A fragments (global, L2-resident) ----
    const uint4* gah = (const uint4*)g_uh;
    const uint4* gal = (const uint4*)g_ul;
#pragma unroll
    for (int it = 0; it < 16; it++) {
        int s = tid + it * 256;
        sAh[s] = gah[s];
        sAl[s] = gal[s];
    }
    // ---- build B fragments: each element converted exactly once ----
#pragma unroll
    for (int j = 0; j < 16; j++) {
        int slot = tid + j * 256;                 // 0..4095
        int l2 = slot & 31, ks = (slot >> 5) & 15, nt = slot >> 9;
        int g = l2 >> 2, tg = l2 & 3;
        long v = (long)v0 + nt * 8 + g;
        float b0 = 0.f, b1 = 0.f;
        if (v < Vv) {
            const float* pb = E3 + v * Dd + ks * 8 + tg;
            b0 = pb[0]; b1 = pb[4];
        }
        uint32_t b0h, b0l, b1h, b1l;
        tf32_split(b0, b0h, b0l);
        tf32_split(b1, b1h, b1l);
        sBf[slot] = make_uint4(b0h, b1h, b0l, b1l);
    }
    __syncthreads();

    float acc[2][4][4];
#pragma unroll
    for (int i = 0; i < 2; i++)
#pragma unroll
        for (int j = 0; j < 4; j++)
#pragma unroll
            for (int k = 0; k < 4; k++) acc[i][j][k] = 0.f;

    const uint4* pAh = sAh + (wm * 2) * 16 * 32 + lane;
    const uint4* pAl = sAl + (wm * 2) * 16 * 32 + lane;
    const uint4* pB  = sBf + (wn * 4) * 16 * 32 + lane;

#pragma unroll 4
    for (int ks = 0; ks < 16; ks++) {
        uint4 ah[2], al[2];
#pragma unroll
        for (int mt = 0; mt < 2; mt++) {
            ah[mt] = pAh[(mt * 16 + ks) * 32];
            al[mt] = pAl[(mt * 16 + ks) * 32];
        }
#pragma unroll
        for (int nt = 0; nt < 4; nt++) {
            uint4 bf = pB[(nt * 16 + ks) * 32];
#pragma unroll
            for (int mt = 0; mt < 2; mt++) {
                MMA_TF32(acc[mt][nt], ah[mt].x, ah[mt].y, ah[mt].z, ah[mt].w, bf.x, bf.y);
                MMA_TF32(acc[mt][nt], ah[mt].x, ah[mt].y, ah[mt].z, ah[mt].w, bf.z, bf.w);
                MMA_TF32(acc[mt][nt], al[mt].x, al[mt].y, al[mt].z, al[mt].w, bf.x, bf.y);
            }
        }
    }

    int g = lane >> 2, tg = lane & 3;
#pragma unroll
    for (int mt = 0; mt < 2; mt++) {
        int m = wm * 32 + mt * 16 + g;
#pragma unroll
        for (int nt = 0; nt < 4; nt++) {
            int v = v0 + wn * 32 + nt * 8 + 2 * tg;
            if (v < Vv) {
                *(float2*)(ahat + (long)m * Vv + v) =
                    make_float2(acc[mt][nt][0], acc[mt][nt][1]);
                *(float2*)(ahat + (long)(m + 8) * Vv + v) =
                    make_float2(acc[mt][nt][2], acc[mt][nt][3]);
            }
        }
    }
}

// ============================================================
// Kernel 5: row softmax over V=50000. grid=B, block=1024.
// ============================================================
__global__ void k_softmax_v(const float* __restrict__ ahat,
                            float* __restrict__ proba) {
    __shared__ float red[32];
    int b = blockIdx.x, tid = threadIdx.x;
    int lane = tid & 31, w = tid >> 5;
    const float* row = ahat + (long)b * Vv;

    float m = -INFINITY;
    for (int v = tid; v < Vv; v += 1024) m = fmaxf(m, row[v]);
#pragma unroll
    for (int o = 16; o; o >>= 1) m = fmaxf(m, __shfl_xor_sync(0xffffffffu, m, o));
    if (lane == 0) red[w] = m;
    __syncthreads();
    if (w == 0) {
        float t = red[lane];
#pragma unroll
        for (int o = 16; o; o >>= 1) t = fmaxf(t, __shfl_xor_sync(0xffffffffu, t, o));
        if (lane == 0) red[0] = t;
    }
    __syncthreads();
    float gmax = red[0];
    __syncthreads();

    float s = 0.f;
    for (int v = tid; v < Vv; v += 1024) s += expf(row[v] - gmax);
#pragma unroll
    for (int o = 16; o; o >>= 1) s += __shfl_xor_sync(0xffffffffu, s, o);
    if (lane == 0) red[w] = s;
    __syncthreads();
    if (w == 0) {
        float t = red[lane];
#pragma unroll
        for (int o = 16; o; o >>= 1) t += __shfl_xor_sync(0xffffffffu, t, o);
        if (lane == 0) red[0] = t;
    }
    __syncthreads();
    float inv = 1.f / red[0];

    float* prow = proba + (long)b * Vv;
    for (int v = tid; v < Vv; v += 1024)
        prow[v] = expf(row[v] - gmax) * inv;
}

// ============================================================
extern "C" void kernel_launch(void* const* d_in, const int* in_sizes, int n_in,
                              void* d_out, int out_size) {
    const int* story = nullptr;
    const int* query = nullptr;
    const float* E = nullptr;
    const float* T = nullptr;
    for (int i = 0; i < n_in; i++) {
        long n = in_sizes[i];
        if (n == (long)Bb * Mm * Ss) story = (const int*)d_in[i];
        else if (n == (long)Bb * Qq) query = (const int*)d_in[i];
        else if (n == (long)NT * Vv * Dd) E = (const float*)d_in[i];
        else if (n == (long)NT * Mm * Dd) T = (const float*)d_in[i];
    }
    float* out = (float*)d_out;
    long BV = (long)Bb * Vv;

    k_query_u<<<Bb, Dd>>>(query, E);
    long nwarps = (long)NT * Bb * Mm;
    k_story_sums<<<(int)(nwarps / SS_WPB), SS_WPB * 32>>>(story, E, T);
    k_hops<<<Bb, 1024>>>();
    k_split_u<<<16, 256>>>();

    const float* E3 = E + (long)(NT - 1) * Vv * Dd;
    cudaFuncSetAttribute(k_gemm_mma, cudaFuncAttributeMaxDynamicSharedMemorySize,
                         GSM2);
    k_gemm_mma<<<(Vv + 63) / 64, 256, GSM2>>>(E3, out);

    if ((long)out_size >= 2 * BV)
        k_softmax_v<<<Bb, 1024>>>(out, out + BV);
}

// round 5
// speedup vs baseline: 1.0147x; 1.0147x over previous
#include <cuda_runtime.h>
#include <math.h>
#include <stdint.h>

#define Bb 128
#define Mm 200
#define Ss 20
#define Qq 20
#define Vv 50000
#define Dd 128
#define NT 4          // max_hops + 1 tables

// -------- device scratch (static allocation; no cudaMalloc allowed) --------
__device__ float g_u[Bb * Dd];                              // 64 KB
__device__ float g_mt[(long)NT * Bb * Mm * Dd];             // 52.4 MB

// ============================================================
// Kernel 1: u = sum over query tokens of E[0] rows.  grid=B, block=D
// ============================================================
__global__ void k_query_u(const int* __restrict__ query,
                          const float* __restrict__ E) {
    int b = blockIdx.x, d = threadIdx.x;
    __shared__ int q[Qq];
    if (d < Qq) q[d] = query[b * Qq + d];
    __syncthreads();
    float acc = 0.f;
#pragma unroll
    for (int i = 0; i < Qq; i++)
        acc += E[(long)q[i] * Dd + d];
    g_u[b * Dd + d] = acc;
}

// ============================================================
// Kernel 2: mt[t][b][i][d] = sum_s E[t][story[b,i,s]][d] + T[t][i][d]
// One warp per (t,b,i), table-major grid (one table hot in L2 at a time).
// ============================================================
#define SS_WPB 8
__global__ void __launch_bounds__(SS_WPB * 32) k_story_sums(
        const int* __restrict__ story,
        const float* __restrict__ E,
        const float* __restrict__ T) {
    long gw = (long)blockIdx.x * SS_WPB + (threadIdx.x >> 5);
    int lane = threadIdx.x & 31;
    int t = (int)(gw / ((long)Bb * Mm));
    int rem = (int)(gw - (long)t * Bb * Mm);
    int b = rem / Mm, i = rem - b * Mm;

    int tok = (lane < Ss) ? story[((long)b * Mm + i) * Ss + lane] : 0;

    const float4* Et = (const float4*)(E + (long)t * Vv * Dd);
    float4 acc = ((const float4*)(T + ((long)t * Mm + i) * Dd))[lane];
#pragma unroll
    for (int s = 0; s < Ss; s++) {
        int id = __shfl_sync(0xffffffffu, tok, s);
        float4 r = Et[(long)id * 32 + lane];
        acc.x += r.x; acc.y += r.y; acc.z += r.z; acc.w += r.w;
    }
    ((float4*)(g_mt + (((long)t * Bb + b) * Mm + i) * Dd))[lane] = acc;
}

// ============================================================
// Kernel 3: all 3 hops fused. grid=B, block=1024. u lives in smem.
// ============================================================
__global__ void __launch_bounds__(1024) k_hops() {
    __shared__ float su[Dd];
    __shared__ float sc[Mm];
    __shared__ float red[32];
    __shared__ float bc[2];
    __shared__ float op[1024];
    int b = blockIdx.x, tid = threadIdx.x;
    int w = tid >> 5, lane = tid & 31;

    if (tid < Dd) su[tid] = g_u[b * Dd + tid];
    __syncthreads();

    for (int hop = 0; hop < NT - 1; hop++) {
        const float* mt = g_mt + (((long)hop * Bb + b) * Mm) * Dd;
        float4 uu = ((const float4*)su)[lane];
        for (int i = w; i < Mm; i += 32) {
            const float4* row = (const float4*)(mt + (long)i * Dd);
            float4 r = row[lane];
            float p = r.x * uu.x + r.y * uu.y + r.z * uu.z + r.w * uu.w;
#pragma unroll
            for (int o = 16; o; o >>= 1) p += __shfl_xor_sync(0xffffffffu, p, o);
            if (lane == 0) sc[i] = p;
        }
        __syncthreads();

        float v = (tid < Mm) ? sc[tid] : -INFINITY;
        float m = v;
#pragma unroll
        for (int o = 16; o; o >>= 1) m = fmaxf(m, __shfl_xor_sync(0xffffffffu, m, o));
        if (lane == 0) red[w] = m;
        __syncthreads();
        if (w == 0) {
            float t = red[lane];
#pragma unroll
            for (int o = 16; o; o >>= 1) t = fmaxf(t, __shfl_xor_sync(0xffffffffu, t, o));
            if (lane == 0) bc[0] = t;
        }
        __syncthreads();
        float e = (tid < Mm) ? expf(v - bc[0]) : 0.f;
        float s = e;
#pragma unroll
        for (int o = 16; o; o >>= 1) s += __shfl_xor_sync(0xffffffffu, s, o);
        if (lane == 0) red[w] = s;
        __syncthreads();
        if (w == 0) {
            float t = red[lane];
#pragma unroll
            for (int o = 16; o; o >>= 1) t += __shfl_xor_sync(0xffffffffu, t, o);
            if (lane == 0) bc[1] = 1.f / t;
        }
        __syncthreads();
        if (tid < Mm) sc[tid] = e * bc[1];
        __syncthreads();

        const float* mtn = g_mt + (((long)(hop + 1) * Bb + b) * Mm) * Dd;
        int part = tid >> 7, d = tid & 127;
        float acc = 0.f;
        int i0 = part * 25;
#pragma unroll
        for (int i = i0; i < i0 + 25; i++)
            acc += sc[i] * mtn[(long)i * Dd + d];
        op[tid] = acc;
        __syncthreads();
        if (tid < Dd) {
            float o = 0.f;
#pragma unroll
            for (int p = 0; p < 8; p++) o += op[p * 128 + tid];
            su[tid] += o;
        }
        __syncthreads();
    }
    if (tid < Dd) g_u[b * Dd + tid] = su[tid];
}

// ============================================================
// tf32 split helpers
// ============================================================
__device__ __forceinline__ void tf32_split(float x, uint32_t& hi, uint32_t& lo) {
    asm("cvt.rna.tf32.f32 %0, %1;" : "=r"(hi) : "f"(x));
    float l = x - __uint_as_float(hi);
    asm("cvt.rna.tf32.f32 %0, %1;" : "=r"(lo) : "f"(l));
}
#define MMA_TF32(c, a0, a1, a2, a3, b0, b1) \
    asm volatile("mma.sync.aligned.m16n8k8.row.col.f32.tf32.tf32.f32 " \
        "{%0,%1,%2,%3}, {%4,%5,%6,%7}, {%8,%9}, {%0,%1,%2,%3};" \
        : "+f"((c)[0]), "+f"((c)[1]), "+f"((c)[2]), "+f"((c)[3]) \
        : "r"(a0), "r"(a1), "r"(a2), "r"(a3), "r"(b0), "r"(b1))

// ============================================================
// Kernel 4: ahat = u @ E3^T, 3xTF32 mma. Asymmetric split:
//  - A (u) in smem f32, split on-the-fly (amortized over 4 n-tiles)
//  - B pre-split ONCE per block into fragment-ordered smem (uint4)
// Block: 128M x 64N, 256 thr (8 warps, 4Mx2N), smem 167KB.
// ============================================================
#define PITCH 132
#define SBF_OFF ((128 + 64) * PITCH)                 // floats before sBf
#define GSM3 (SBF_OFF * 4 + 4096 * 16)               // 101376 + 65536 B

__global__ void __launch_bounds__(256, 1)
k_gemm_mma(const float* __restrict__ E3, float* __restrict__ ahat) {
    extern __shared__ float sm[];
    float* sA = sm;                        // [128][PITCH] f32 (u)
    float* sB = sm + 128 * PITCH;          // [64][PITCH]  f32 staging
    uint4* sBf = (uint4*)(sm + SBF_OFF);   // [8nt][16ks][32lane] {b0h,b1h,b0l,b1l}
    int tid = threadIdx.x, lane = tid & 31, wid = tid >> 5;
    int wm = wid & 3, wn = wid >> 2;
    int v0 = blockIdx.x * 64;

    // ---- stage A (coalesced) ----
    const float4* gu = (const float4*)g_u;
#pragma unroll
    for (int it = 0; it < 16; it++) {
        int e = tid + it * 256;
        int row = e >> 5, c4 = e & 31;
        *(float4*)(sA + row * PITCH + c4 * 4) = gu[e];
    }
    // ---- stage B tile (coalesced, zero-pad past V) ----
    const float4* ge = (const float4*)E3;
#pragma unroll
    for (int it = 0; it < 8; it++) {
        int e = tid + it * 256;
        int row = e >> 5, c4 = e & 31;
        long v = (long)v0 + row;
        float4 val = (v < Vv) ? ge[v * 32 + c4] : make_float4(0.f, 0.f, 0.f, 0.f);
        *(float4*)(sB + row * PITCH + c4 * 4) = val;
    }
    __syncthreads();

    // ---- build B fragments: each element split exactly once ----
#pragma unroll
    for (int j = 0; j < 16; j++) {
        int slot = tid + j * 256;                 // 0..4095
        int l2 = slot & 31, ks = (slot >> 5) & 15, nt = slot >> 9;
        int g = l2 >> 2, tg = l2 & 3;
        const float* pb = sB + (nt * 8 + g) * PITCH + ks * 8 + tg;
        uint32_t b0h, b0l, b1h, b1l;
        tf32_split(pb[0], b0h, b0l);
        tf32_split(pb[4], b1h, b1l);
        sBf[slot] = make_uint4(b0h, b1h, b0l, b1l);
    }
    __syncthreads();

    float acc[2][4][4];
#pragma unroll
    for (int i = 0; i < 2; i++)
#pragma unroll
        for (int j = 0; j < 4; j++)
#pragma unroll
            for (int k = 0; k < 4; k++) acc[i][j][k] = 0.f;

    int g = lane >> 2, tg = lane & 3;
    const float* pA = sA + (wm * 32 + g) * PITCH + tg;
    const uint4* pB = sBf + (wn * 4) * 16 * 32 + lane;

#pragma unroll 4
    for (int ks = 0; ks < 16; ks++) {
        int k0 = ks * 8;
        // A fragments: load f32 + split (hoisted over the 4 n-tiles)
        uint32_t ah[2][4], al[2][4];
#pragma unroll
        for (int mt = 0; mt < 2; mt++) {
            const float* pr = pA + mt * 16 * PITCH;
            tf32_split(pr[k0],             ah[mt][0], al[mt][0]);
            tf32_split(pr[8 * PITCH + k0], ah[mt][1], al[mt][1]);
            tf32_split(pr[k0 + 4],         ah[mt][2], al[mt][2]);
            tf32_split(pr[8 * PITCH + k0 + 4], ah[mt][3], al[mt][3]);
        }
#pragma unroll
        for (int nt = 0; nt < 4; nt++) {
            uint4 bf = pB[(nt * 16 + ks) * 32];
#pragma unroll
            for (int mt = 0; mt < 2; mt++) {
                MMA_TF32(acc[mt][nt], ah[mt][0], ah[mt][1], ah[mt][2], ah[mt][3], bf.x, bf.y);
                MMA_TF32(acc[mt][nt], ah[mt][0], ah[mt][1], ah[mt][2], ah[mt][3], bf.z, bf.w);
                MMA_TF32(acc[mt][nt], al[mt][0], al[mt][1], al[mt][2], al[mt][3], bf.x, bf.y);
            }
        }
    }

    // ---- epilogue ----
#pragma unroll
    for (int mt = 0; mt < 2; mt++) {
        int m = wm * 32 + mt * 16 + g;
#pragma unroll
        for (int nt = 0; nt < 4; nt++) {
            int v = v0 + wn * 32 + nt * 8 + 2 * tg;
            if (v < Vv) {
                *(float2*)(ahat + (long)m * Vv + v) =
                    make_float2(acc[mt][nt][0], acc[mt][nt][1]);
                *(float2*)(ahat + (long)(m + 8) * Vv + v) =
                    make_float2(acc[mt][nt][2], acc[mt][nt][3]);
            }
        }
    }
}

// ============================================================
// Kernel 5: row softmax over V=50000. grid=B, block=1024.
// ============================================================
__global__ void k_softmax_v(const float* __restrict__ ahat,
                            float* __restrict__ proba) {
    __shared__ float red[32];
    int b = blockIdx.x, tid = threadIdx.x;
    int lane = tid & 31, w = tid >> 5;
    const float* row = ahat + (long)b * Vv;

    float m = -INFINITY;
    for (int v = tid; v < Vv; v += 1024) m = fmaxf(m, row[v]);
#pragma unroll
    for (int o = 16; o; o >>= 1) m = fmaxf(m, __shfl_xor_sync(0xffffffffu, m, o));
    if (lane == 0) red[w] = m;
    __syncthreads();
    if (w == 0) {
        float t = red[lane];
#pragma unroll
        for (int o = 16; o; o >>= 1) t = fmaxf(t, __shfl_xor_sync(0xffffffffu, t, o));
        if (lane == 0) red[0] = t;
    }
    __syncthreads();
    float gmax = red[0];
    __syncthreads();

    float s = 0.f;
    for (int v = tid; v < Vv; v += 1024) s += expf(row[v] - gmax);
#pragma unroll
    for (int o = 16; o; o >>= 1) s += __shfl_xor_sync(0xffffffffu, s, o);
    if (lane == 0) red[w] = s;
    __syncthreads();
    if (w == 0) {
        float t = red[lane];
#pragma unroll
        for (int o = 16; o; o >>= 1) t += __shfl_xor_sync(0xffffffffu, t, o);
        if (lane == 0) red[0] = t;
    }
    __syncthreads();
    float inv = 1.f / red[0];

    float* prow = proba + (long)b * Vv;
    for (int v = tid; v < Vv; v += 1024)
        prow[v] = expf(row[v] - gmax) * inv;
}

// ============================================================
extern "C" void kernel_launch(void* const* d_in, const int* in_sizes, int n_in,
                              void* d_out, int out_size) {
    const int* story = nullptr;
    const int* query = nullptr;
    const float* E = nullptr;
    const float* T = nullptr;
    for (int i = 0; i < n_in; i++) {
        long n = in_sizes[i];
        if (n == (long)Bb * Mm * Ss) story = (const int*)d_in[i];
        else if (n == (long)Bb * Qq) query = (const int*)d_in[i];
        else if (n == (long)NT * Vv * Dd) E = (const float*)d_in[i];
        else if (n == (long)NT * Mm * Dd) T = (const float*)d_in[i];
    }
    float* out = (float*)d_out;
    long BV = (long)Bb * Vv;

    k_query_u<<<Bb, Dd>>>(query, E);
    long nwarps = (long)NT * Bb * Mm;
    k_story_sums<<<(int)(nwarps / SS_WPB), SS_WPB * 32>>>(story, E, T);
    k_hops<<<Bb, 1024>>>();

    const float* E3 = E + (long)(NT - 1) * Vv * Dd;
    cudaFuncSetAttribute(k_gemm_mma, cudaFuncAttributeMaxDynamicSharedMemorySize,
                         GSM3);
    k_gemm_mma<<<(Vv + 63) / 64, 256, GSM3>>>(E3, out);

    if ((long)out_size >= 2 * BV)
        k_softmax_v<<<Bb, 1024>>>(out, out + BV);
}

// round 6
// speedup vs baseline: 1.0639x; 1.0485x over previous
#include <cuda_runtime.h>
#include <math.h>
#include <stdint.h>

#define Bb 128
#define Mm 200
#define Ss 20
#define Qq 20
#define Vv 50000
#define Dd 128
#define NT 4          // max_hops + 1 tables

// -------- device scratch (static allocation; no cudaMalloc allowed) --------
__device__ float g_u[Bb * Dd];                              // 64 KB
__device__ float g_mt[(long)NT * Bb * Mm * Dd];             // 52.4 MB

// ============================================================
// Kernel 1: u = sum over query tokens of E[0] rows.  grid=B, block=D
// ============================================================
__global__ void k_query_u(const int* __restrict__ query,
                          const float* __restrict__ E) {
    int b = blockIdx.x, d = threadIdx.x;
    __shared__ int q[Qq];
    if (d < Qq) q[d] = query[b * Qq + d];
    __syncthreads();
    float acc = 0.f;
#pragma unroll
    for (int i = 0; i < Qq; i++)
        acc += E[(long)q[i] * Dd + d];
    g_u[b * Dd + d] = acc;
}

// ============================================================
// Kernel 2: mt[t][b][i][d] = sum_s E[t][story[b,i,s]][d] + T[t][i][d]
// One warp per (t,b,i), table-major grid (one table hot in L2 at a time).
// ============================================================
#define SS_WPB 8
__global__ void __launch_bounds__(SS_WPB * 32) k_story_sums(
        const int* __restrict__ story,
        const float* __restrict__ E,
        const float* __restrict__ T) {
    long gw = (long)blockIdx.x * SS_WPB + (threadIdx.x >> 5);
    int lane = threadIdx.x & 31;
    int t = (int)(gw / ((long)Bb * Mm));
    int rem = (int)(gw - (long)t * Bb * Mm);
    int b = rem / Mm, i = rem - b * Mm;

    int tok = (lane < Ss) ? story[((long)b * Mm + i) * Ss + lane] : 0;

    const float4* Et = (const float4*)(E + (long)t * Vv * Dd);
    float4 acc = ((const float4*)(T + ((long)t * Mm + i) * Dd))[lane];
#pragma unroll
    for (int s = 0; s < Ss; s++) {
        int id = __shfl_sync(0xffffffffu, tok, s);
        float4 r = Et[(long)id * 32 + lane];
        acc.x += r.x; acc.y += r.y; acc.z += r.z; acc.w += r.w;
    }
    ((float4*)(g_mt + (((long)t * Bb + b) * Mm + i) * Dd))[lane] = acc;
}

// ============================================================
// Kernel 3: all 3 hops fused. grid=B, block=1024. u lives in smem.
// ============================================================
__global__ void __launch_bounds__(1024) k_hops() {
    __shared__ float su[Dd];
    __shared__ float sc[Mm];
    __shared__ float red[32];
    __shared__ float bc[2];
    __shared__ float op[1024];
    int b = blockIdx.x, tid = threadIdx.x;
    int w = tid >> 5, lane = tid & 31;

    if (tid < Dd) su[tid] = g_u[b * Dd + tid];
    __syncthreads();

    for (int hop = 0; hop < NT - 1; hop++) {
        const float* mt = g_mt + (((long)hop * Bb + b) * Mm) * Dd;
        float4 uu = ((const float4*)su)[lane];
        for (int i = w; i < Mm; i += 32) {
            const float4* row = (const float4*)(mt + (long)i * Dd);
            float4 r = row[lane];
            float p = r.x * uu.x + r.y * uu.y + r.z * uu.z + r.w * uu.w;
#pragma unroll
            for (int o = 16; o; o >>= 1) p += __shfl_xor_sync(0xffffffffu, p, o);
            if (lane == 0) sc[i] = p;
        }
        __syncthreads();

        float v = (tid < Mm) ? sc[tid] : -INFINITY;
        float m = v;
#pragma unroll
        for (int o = 16; o; o >>= 1) m = fmaxf(m, __shfl_xor_sync(0xffffffffu, m, o));
        if (lane == 0) red[w] = m;
        __syncthreads();
        if (w == 0) {
            float t = red[lane];
#pragma unroll
            for (int o = 16; o; o >>= 1) t = fmaxf(t, __shfl_xor_sync(0xffffffffu, t, o));
            if (lane == 0) bc[0] = t;
        }
        __syncthreads();
        float e = (tid < Mm) ? expf(v - bc[0]) : 0.f;
        float s = e;
#pragma unroll
        for (int o = 16; o; o >>= 1) s += __shfl_xor_sync(0xffffffffu, s, o);
        if (lane == 0) red[w] = s;
        __syncthreads();
        if (w == 0) {
            float t = red[lane];
#pragma unroll
            for (int o = 16; o; o >>= 1) t += __shfl_xor_sync(0xffffffffu, t, o);
            if (lane == 0) bc[1] = 1.f / t;
        }
        __syncthreads();
        if (tid < Mm) sc[tid] = e * bc[1];
        __syncthreads();

        const float* mtn = g_mt + (((long)(hop + 1) * Bb + b) * Mm) * Dd;
        int part = tid >> 7, d = tid & 127;
        float acc = 0.f;
        int i0 = part * 25;
#pragma unroll
        for (int i = i0; i < i0 + 25; i++)
            acc += sc[i] * mtn[(long)i * Dd + d];
        op[tid] = acc;
        __syncthreads();
        if (tid < Dd) {
            float o = 0.f;
#pragma unroll
            for (int p = 0; p < 8; p++) o += op[p * 128 + tid];
            su[tid] += o;
        }
        __syncthreads();
    }
    if (tid < Dd) g_u[b * Dd + tid] = su[tid];
}

// ============================================================
// tf32 split helpers
// ============================================================
__device__ __forceinline__ void tf32_split(float x, uint32_t& hi, uint32_t& lo) {
    asm("cvt.rna.tf32.f32 %0, %1;" : "=r"(hi) : "f"(x));
    float l = x - __uint_as_float(hi);
    asm("cvt.rna.tf32.f32 %0, %1;" : "=r"(lo) : "f"(l));
}
#define MMA_TF32(c, a0, a1, a2, a3, b0, b1) \
    asm volatile("mma.sync.aligned.m16n8k8.row.col.f32.tf32.tf32.f32 " \
        "{%0,%1,%2,%3}, {%4,%5,%6,%7}, {%8,%9}, {%0,%1,%2,%3};" \
        : "+f"((c)[0]), "+f"((c)[1]), "+f"((c)[2]), "+f"((c)[3]) \
        : "r"(a0), "r"(a1), "r"(a2), "r"(a3), "r"(b0), "r"(b1))

// ============================================================
// Kernel 4: ahat = u @ E3^T, 3xTF32 mma, R3 mainloop, K CHUNKED (2x64)
// so smem = 52KB/CTA -> 2 CTAs/SM (regs capped at 128 by launch_bounds).
// Block: 128M x 64N, 256 thr (8 warps as 4Mx2N, each 32Mx32N).
// ============================================================
#define KC 64                     // k-chunk
#define CPITCH (KC + 4)           // 68 floats, conflict-free
#define GSM4 ((128 + 64) * CPITCH * 4)   // 52,224 B

__global__ void __launch_bounds__(256, 2)
k_gemm_mma(const float* __restrict__ E3, float* __restrict__ ahat) {
    extern __shared__ float sm[];
    float* sA = sm;                     // [128][CPITCH]
    float* sB = sm + 128 * CPITCH;      // [64][CPITCH]
    int tid = threadIdx.x, lane = tid & 31, wid = tid >> 5;
    int wm = wid & 3, wn = wid >> 2;
    int v0 = blockIdx.x * 64;

    float acc[2][4][4];
#pragma unroll
    for (int i = 0; i < 2; i++)
#pragma unroll
        for (int j = 0; j < 4; j++)
#pragma unroll
            for (int k = 0; k < 4; k++) acc[i][j][k] = 0.f;

    int g = lane >> 2, tg = lane & 3;
    const float4* gu = (const float4*)g_u;
    const float4* ge = (const float4*)E3;

#pragma unroll
    for (int kc = 0; kc < 2; kc++) {
        // ---- stage A chunk: 128 rows x 64 k (2048 float4) ----
#pragma unroll
        for (int it = 0; it < 8; it++) {
            int e = tid + it * 256;
            int row = e >> 4, c4 = e & 15;
            *(float4*)(sA + row * CPITCH + c4 * 4) = gu[row * 32 + kc * 16 + c4];
        }
        // ---- stage B chunk: 64 rows x 64 k (1024 float4) ----
#pragma unroll
        for (int it = 0; it < 4; it++) {
            int e = tid + it * 256;
            int row = e >> 4, c4 = e & 15;
            long v = (long)v0 + row;
            float4 val = (v < Vv) ? ge[v * 32 + kc * 16 + c4]
                                  : make_float4(0.f, 0.f, 0.f, 0.f);
            *(float4*)(sB + row * CPITCH + c4 * 4) = val;
        }
        __syncthreads();

        const float* pA = sA + (wm * 32 + g) * CPITCH + tg;
        const float* pBs = sB + (wn * 32 + g) * CPITCH + tg;

#pragma unroll
        for (int ks = 0; ks < 8; ks++) {
            int k0 = ks * 8;
            uint32_t ah[2][4], al[2][4];
#pragma unroll
            for (int mt = 0; mt < 2; mt++) {
                const float* pr = pA + mt * 16 * CPITCH;
                tf32_split(pr[k0],                 ah[mt][0], al[mt][0]);
                tf32_split(pr[8 * CPITCH + k0],    ah[mt][1], al[mt][1]);
                tf32_split(pr[k0 + 4],             ah[mt][2], al[mt][2]);
                tf32_split(pr[8 * CPITCH + k0 + 4], ah[mt][3], al[mt][3]);
            }
#pragma unroll
            for (int nt = 0; nt < 4; nt++) {
                const float* pb = pBs + nt * 8 * CPITCH;
                float b0 = pb[k0], b1 = pb[k0 + 4];
                uint32_t bh0, bl0, bh1, bl1;
                tf32_split(b0, bh0, bl0);
                tf32_split(b1, bh1, bl1);
#pragma unroll
                for (int mt = 0; mt < 2; mt++) {
                    MMA_TF32(acc[mt][nt], ah[mt][0], ah[mt][1], ah[mt][2], ah[mt][3], bh0, bh1);
                    MMA_TF32(acc[mt][nt], ah[mt][0], ah[mt][1], ah[mt][2], ah[mt][3], bl0, bl1);
                    MMA_TF32(acc[mt][nt], al[mt][0], al[mt][1], al[mt][2], al[mt][3], bh0, bh1);
                }
            }
        }
        __syncthreads();
    }

    // ---- epilogue ----
#pragma unroll
    for (int mt = 0; mt < 2; mt++) {
        int m = wm * 32 + mt * 16 + g;
#pragma unroll
        for (int nt = 0; nt < 4; nt++) {
            int v = v0 + wn * 32 + nt * 8 + 2 * tg;
            if (v < Vv) {
                *(float2*)(ahat + (long)m * Vv + v) =
                    make_float2(acc[mt][nt][0], acc[mt][nt][1]);
                *(float2*)(ahat + (long)(m + 8) * Vv + v) =
                    make_float2(acc[mt][nt][2], acc[mt][nt][3]);
            }
        }
    }
}

// ============================================================
// Kernel 5: row softmax over V=50000. grid=B, block=1024.
// ============================================================
__global__ void k_softmax_v(const float* __restrict__ ahat,
                            float* __restrict__ proba) {
    __shared__ float red[32];
    int b = blockIdx.x, tid = threadIdx.x;
    int lane = tid & 31, w = tid >> 5;
    const float* row = ahat + (long)b * Vv;

    float m = -INFINITY;
    for (int v = tid; v < Vv; v += 1024) m = fmaxf(m, row[v]);
#pragma unroll
    for (int o = 16; o; o >>= 1) m = fmaxf(m, __shfl_xor_sync(0xffffffffu, m, o));
    if (lane == 0) red[w] = m;
    __syncthreads();
    if (w == 0) {
        float t = red[lane];
#pragma unroll
        for (int o = 16; o; o >>= 1) t = fmaxf(t, __shfl_xor_sync(0xffffffffu, t, o));
        if (lane == 0) red[0] = t;
    }
    __syncthreads();
    float gmax = red[0];
    __syncthreads();

    float s = 0.f;
    for (int v = tid; v < Vv; v += 1024) s += expf(row[v] - gmax);
#pragma unroll
    for (int o = 16; o; o >>= 1) s += __shfl_xor_sync(0xffffffffu, s, o);
    if (lane == 0) red[w] = s;
    __syncthreads();
    if (w == 0) {
        float t = red[lane];
#pragma unroll
        for (int o = 16; o; o >>= 1) t += __shfl_xor_sync(0xffffffffu, t, o);
        if (lane == 0) red[0] = t;
    }
    __syncthreads();
    float inv = 1.f / red[0];

    float* prow = proba + (long)b * Vv;
    for (int v = tid; v < Vv; v += 1024)
        prow[v] = expf(row[v] - gmax) * inv;
}

// ============================================================
extern "C" void kernel_launch(void* const* d_in, const int* in_sizes, int n_in,
                              void* d_out, int out_size) {
    const int* story = nullptr;
    const int* query = nullptr;
    const float* E = nullptr;
    const float* T = nullptr;
    for (int i = 0; i < n_in; i++) {
        long n = in_sizes[i];
        if (n == (long)Bb * Mm * Ss) story = (const int*)d_in[i];
        else if (n == (long)Bb * Qq) query = (const int*)d_in[i];
        else if (n == (long)NT * Vv * Dd) E = (const float*)d_in[i];
        else if (n == (long)NT * Mm * Dd) T = (const float*)d_in[i];
    }
    float* out = (float*)d_out;
    long BV = (long)Bb * Vv;

    k_query_u<<<Bb, Dd>>>(query, E);
    long nwarps = (long)NT * Bb * Mm;
    k_story_sums<<<(int)(nwarps / SS_WPB), SS_WPB * 32>>>(story, E, T);
    k_hops<<<Bb, 1024>>>();

    const float* E3 = E + (long)(NT - 1) * Vv * Dd;
    cudaFuncSetAttribute(k_gemm_mma, cudaFuncAttributeMaxDynamicSharedMemorySize,
                         GSM4);
    k_gemm_mma<<<(Vv + 63) / 64, 256, GSM4>>>(E3, out);

    if ((long)out_size >= 2 * BV)
        k_softmax_v<<<Bb, 1024>>>(out, out + BV);
}